// round 16
// baseline (speedup 1.0000x reference)
#include <cuda_runtime.h>
#include <cuda_fp16.h>
#include <math.h>

#define BATCH 4
#define SEQ 2048
#define DMODEL 256
#define NHEAD 8
#define DHEAD 32
#define NLAYER 4
#define ROWS (BATCH*SEQ)   // 8192

// ---------------- scratch ----------------
__device__ float  g_h   [ROWS*DMODEL];
__device__ __half g_hh  [ROWS*DMODEL];
__device__ __half g_qkvh[ROWS*3*DMODEL];
__device__ __half g_oh  [ROWS*DMODEL];
__device__ __half g_ffnh[ROWS*2*DMODEL];
__device__ float  g_cs  [ROWS*32];
__device__ float  g_bf  [NLAYER*DMODEL];
__device__ __half g_wqkv [NLAYER*DMODEL*3*DMODEL];
__device__ __half g_wffn1[NLAYER*DMODEL*2*DMODEL];
__device__ __half g_wffn2[NLAYER*2*DMODEL*DMODEL];
__device__ __half g_wfin [DMODEL*DMODEL];
__device__ __half g_wWf  [NLAYER*DMODEL*DMODEL];

// ---------------- helpers ----------------
__device__ __forceinline__ unsigned ph2(float a, float b) {
    __half2 h = __floats2half2_rn(a, b);
    return *reinterpret_cast<unsigned*>(&h);
}

__device__ __forceinline__ float ex2(float x) {
    float y; asm("ex2.approx.ftz.f32 %0, %1;" : "=f"(y) : "f"(x)); return y;
}

__device__ __forceinline__ void mma_h(float* d, const unsigned* a, unsigned b0, unsigned b1) {
    asm("mma.sync.aligned.m16n8k16.row.col.f32.f16.f16.f32 "
        "{%0,%1,%2,%3},{%4,%5,%6,%7},{%8,%9},{%0,%1,%2,%3};"
        : "+f"(d[0]), "+f"(d[1]), "+f"(d[2]), "+f"(d[3])
        : "r"(a[0]), "r"(a[1]), "r"(a[2]), "r"(a[3]), "r"(b0), "r"(b1));
}

__device__ __forceinline__ void ldsm4(unsigned* r, const void* p) {
    unsigned a = (unsigned)__cvta_generic_to_shared(p);
    asm volatile("ldmatrix.sync.aligned.m8n8.x4.shared.b16 {%0,%1,%2,%3}, [%4];"
        : "=r"(r[0]), "=r"(r[1]), "=r"(r[2]), "=r"(r[3]) : "r"(a));
}

__device__ __forceinline__ void ldsm4t(unsigned* r, const void* p) {
    unsigned a = (unsigned)__cvta_generic_to_shared(p);
    asm volatile("ldmatrix.sync.aligned.m8n8.x4.trans.shared.b16 {%0,%1,%2,%3}, [%4];"
        : "=r"(r[0]), "=r"(r[1]), "=r"(r[2]), "=r"(r[3]) : "r"(a));
}

__device__ __forceinline__ void cpa16(void* smem, const void* gmem) {
    unsigned s = (unsigned)__cvta_generic_to_shared(smem);
    asm volatile("cp.async.ca.shared.global [%0], [%1], 16;" :: "r"(s), "l"(gmem));
}
__device__ __forceinline__ void cp_commit() { asm volatile("cp.async.commit_group;"); }
__device__ __forceinline__ void cp_wait0() { asm volatile("cp.async.wait_group 0;"); }
__device__ __forceinline__ void cp_wait1() { asm volatile("cp.async.wait_group 1;"); }

// ---------------- one-shot weight conversion fp32 -> fp16 ----------------
#define NQ  (NLAYER*DMODEL*3*DMODEL)
#define NF1 (NLAYER*DMODEL*2*DMODEL)
#define NF2 (NLAYER*2*DMODEL*DMODEL)
#define NFW (DMODEL*DMODEL)
__global__ void conv_w(const float* __restrict__ qw, const float* __restrict__ f1,
                       const float* __restrict__ f2, const float* __restrict__ fw,
                       __half* __restrict__ dq, __half* __restrict__ d1,
                       __half* __restrict__ d2, __half* __restrict__ df) {
    int i = (blockIdx.x*256 + threadIdx.x)*8;
    const float* s; __half* d;
    if (i < NQ)                { s = qw + i;                  d = dq + i; }
    else if (i < NQ+NF1)       { s = f1 + (i-NQ);             d = d1 + (i-NQ); }
    else if (i < NQ+NF1+NF2)   { s = f2 + (i-NQ-NF1);         d = d2 + (i-NQ-NF1); }
    else                       { s = fw + (i-NQ-NF1-NF2);     d = df + (i-NQ-NF1-NF2); }
    float4 a = *(const float4*)s;
    float4 b = *(const float4*)(s + 4);
    *(uint4*)d = make_uint4(ph2(a.x,a.y), ph2(a.z,a.w), ph2(b.x,b.y), ph2(b.z,b.w));
}

// ---------------- fused setup: proj (+fp16 mirror) + freqs ----------------
__global__ void setup_kernel(const float* __restrict__ hin, const float* __restrict__ pw,
                             const float* __restrict__ pb, float* __restrict__ hout,
                             __half* __restrict__ houth,
                             const float* __restrict__ pos, float* __restrict__ cs) {
    int bid = blockIdx.x;
    if (bid < ROWS*64/256) {
        int idx = bid*256 + threadIdx.x;
        int row = idx >> 6, c4 = idx & 63;
        float4 w = ((const float4*)pw)[c4];
        float4 b = ((const float4*)pb)[c4];
        float hv = hin[row];
        float4 r; r.x = hv*w.x + b.x; r.y = hv*w.y + b.y; r.z = hv*w.z + b.z; r.w = hv*w.w + b.w;
        ((float4*)hout)[row*64 + c4] = r;
        *(uint2*)&houth[row*DMODEL + c4*4] = make_uint2(ph2(r.x,r.y), ph2(r.z,r.w));
    } else {
        int idx = (bid - ROWS*64/256)*256 + threadIdx.x;
        int row = idx >> 4; int r = idx & 15; int axis = r >> 3; int fi = r & 7;
        float coord = pos[row*2 + axis];
        float inv = powf(10000.f, -(float)fi * 0.125f);
        float ang = coord * 64.f * inv;
        float s, c; sincosf(ang, &s, &c);
        cs[row*32 + axis*16 + fi]     = c;
        cs[row*32 + axis*16 + 8 + fi] = s;
    }
}

__global__ void fuse_bias_kernel(const float* __restrict__ out_b, const float* __restrict__ O_w,
                                 const float* __restrict__ O_b, float* __restrict__ bf) {
    int l = blockIdx.x, j = threadIdx.x;
    const float* wb = O_w + (size_t)l*DMODEL*DMODEL;
    const float* ob = out_b + l*DMODEL;
    float acc = O_b[l*DMODEL + j];
    for (int i = 0; i < DMODEL; i++) acc = fmaf(ob[i], wb[i*DMODEL + j], acc);
    bf[l*DMODEL + j] = acc;
}

// ---------------- pure-fp16 GEMM with optional fused rope epilogue ----------------
template<int HASB, int RELU, int OUTH, int ROPE>
__global__ void __launch_bounds__(256) gemm_hh(const __half* __restrict__ A, const __half* __restrict__ W,
                                               const float* __restrict__ bias, void* __restrict__ Cv,
                                               const float* __restrict__ cs,
                                               int M, int K, int N) {
    __shared__ __half Ah[2][128*40];
    __shared__ __half Bh[2][32*136];
    int bm = blockIdx.y*128, bn = blockIdx.x*128;
    int tid = threadIdx.x, lane = tid & 31, warp = tid >> 5;
    int q = lane >> 2, t = lane & 3;
    int g8 = lane >> 3, il8 = lane & 7;
    int wm = (warp >> 2)*64, wn = (warp & 3)*32;
    float acc[4][4][4] = {};

    int arow = tid >> 1, aseg = (tid & 1)*2;
    int brow = tid >> 4, bseg = tid & 15;
    const __half* Abase = A + (size_t)(bm + arow)*K;
    const __half* Wb0 = W + (size_t)brow*N + bn + bseg*8;
    const __half* Wb1 = W + (size_t)(brow + 16)*N + bn + bseg*8;

    cpa16(&Ah[0][arow*40 + aseg*8],     Abase + aseg*8);
    cpa16(&Ah[0][arow*40 + (aseg+1)*8], Abase + (aseg+1)*8);
    cpa16(&Bh[0][brow*136 + bseg*8], Wb0);
    cpa16(&Bh[0][(brow+16)*136 + bseg*8], Wb1);
    cp_commit();

    int buf = 0;
    for (int k0 = 0; k0 < K; k0 += 32) {
        bool more = (k0 + 32) < K;
        if (more) {
            int nb = buf ^ 1;
            cpa16(&Ah[nb][arow*40 + aseg*8],     Abase + k0 + 32 + aseg*8);
            cpa16(&Ah[nb][arow*40 + (aseg+1)*8], Abase + k0 + 32 + (aseg+1)*8);
            cpa16(&Bh[nb][brow*136 + bseg*8],      Wb0 + (size_t)(k0+32)*N);
            cpa16(&Bh[nb][(brow+16)*136 + bseg*8], Wb1 + (size_t)(k0+32)*N);
            cp_commit();
            cp_wait1();
        } else {
            cp_wait0();
        }
        __syncthreads();

#pragma unroll
        for (int ks = 0; ks < 2; ks++) {
            unsigned af[4][4];
#pragma unroll
            for (int mt = 0; mt < 4; mt++)
                ldsm4(af[mt], &Ah[buf][(wm + mt*16 + (g8 & 1)*8 + il8)*40 + ks*16 + (g8 >> 1)*8]);
#pragma unroll
            for (int ntp = 0; ntp < 2; ntp++) {
                unsigned bb[4];
                ldsm4t(bb, &Bh[buf][(ks*16 + (lane & 15))*136 + wn + ntp*16 + (lane >> 4)*8]);
#pragma unroll
                for (int mt = 0; mt < 4; mt++) {
                    mma_h(acc[mt][2*ntp],   af[mt], bb[0], bb[1]);
                    mma_h(acc[mt][2*ntp+1], af[mt], bb[2], bb[3]);
                }
            }
        }
        __syncthreads();
        buf ^= 1;
    }

    if (ROPE && bn < 512) {
        float scl = (bn < 256) ? 0.25503472f : 1.0f;
        __half* Ch = (__half*)Cv;
#pragma unroll
        for (int mt = 0; mt < 4; mt++) {
            int r0 = bm + wm + mt*16 + q;
            const float* cr0 = cs + (size_t)r0*32;
            const float* cr1 = cs + (size_t)(r0+8)*32;
#pragma unroll
            for (int pp = 0; pp < 2; pp++) {
                int lo = pp*2, hi = pp*2 + 1;
                int off = pp*16 + 2*t;
                float2 c0p = *(const float2*)&cr0[off];
                float2 s0p = *(const float2*)&cr0[off+8];
                float2 c1p = *(const float2*)&cr1[off];
                float2 s1p = *(const float2*)&cr1[off+8];
                float l0 = acc[mt][lo][0], l1 = acc[mt][lo][1];
                float l2 = acc[mt][lo][2], l3 = acc[mt][lo][3];
                float u0 = acc[mt][hi][0], u1 = acc[mt][hi][1];
                float u2 = acc[mt][hi][2], u3 = acc[mt][hi][3];
                float nl0 = (l0*c0p.x - u0*s0p.x)*scl, nl1 = (l1*c0p.y - u1*s0p.y)*scl;
                float nl2 = (l2*c1p.x - u2*s1p.x)*scl, nl3 = (l3*c1p.y - u3*s1p.y)*scl;
                float nu0 = (u0*c0p.x + l0*s0p.x)*scl, nu1 = (u1*c0p.y + l1*s0p.y)*scl;
                float nu2 = (u2*c1p.x + l2*s1p.x)*scl, nu3 = (u3*c1p.y + l3*s1p.y)*scl;
                int cl = bn + wn + lo*8 + 2*t;
                int ch = bn + wn + hi*8 + 2*t;
                *(unsigned*)&Ch[(size_t)r0*N + cl]     = ph2(nl0, nl1);
                *(unsigned*)&Ch[(size_t)(r0+8)*N + cl] = ph2(nl2, nl3);
                *(unsigned*)&Ch[(size_t)r0*N + ch]     = ph2(nu0, nu1);
                *(unsigned*)&Ch[(size_t)(r0+8)*N + ch] = ph2(nu2, nu3);
            }
        }
        return;
    }

#pragma unroll
    for (int mt = 0; mt < 4; mt++) {
        int r0 = bm + wm + mt*16 + q;
#pragma unroll
        for (int nt = 0; nt < 4; nt++) {
            int c0 = bn + wn + nt*8 + 2*t;
            float b0 = 0.f, b1 = 0.f;
            if (HASB) { b0 = bias[c0]; b1 = bias[c0+1]; }
            float v0 = acc[mt][nt][0] + b0, v1 = acc[mt][nt][1] + b1;
            float v2 = acc[mt][nt][2] + b0, v3 = acc[mt][nt][3] + b1;
            if (RELU) { v0=fmaxf(v0,0.f); v1=fmaxf(v1,0.f); v2=fmaxf(v2,0.f); v3=fmaxf(v3,0.f); }
            if (OUTH) {
                __half* Ch = (__half*)Cv;
                *(unsigned*)&Ch[(size_t)r0*N + c0]     = ph2(v0, v1);
                *(unsigned*)&Ch[(size_t)(r0+8)*N + c0] = ph2(v2, v3);
            } else {
                float* C = (float*)Cv;
                float2 w0; w0.x = v0; w0.y = v1;
                float2 w1; w1.x = v2; w1.y = v3;
                *(float2*)&C[(size_t)r0*N + c0]     = w0;
                *(float2*)&C[(size_t)(r0+8)*N + c0] = w1;
            }
        }
    }
}

// ---------------- fused GEMM + bias + residual + LN ----------------
__global__ void __launch_bounds__(256) gemm_ln(const __half* __restrict__ A, const __half* __restrict__ W,
                                               const float* __restrict__ bias,
                                               const float* __restrict__ g, const float* __restrict__ bb,
                                               float* __restrict__ h, __half* __restrict__ hh, int K) {
    __shared__ __half Ah[2][64*40];
    __shared__ __half Bh[2][32*264];
    __shared__ float red1[64*4], red2[64*4];
    int bm = blockIdx.x*64;
    int tid = threadIdx.x, lane = tid & 31, warp = tid >> 5;
    int q = lane >> 2, t = lane & 3;
    int g8 = lane >> 3, il8 = lane & 7;
    int wm = (warp >> 2)*32, wn = (warp & 3)*64;
    float acc[2][8][4] = {};

    int arow = tid >> 2, aseg = tid & 3;
    const __half* Abase = A + (size_t)(bm + arow)*K;
    int bwrow = warp, bwseg = lane;

    cpa16(&Ah[0][arow*40 + aseg*8], Abase + aseg*8);
#pragma unroll
    for (int j = 0; j < 4; j++) {
        int br = j*8 + bwrow;
        cpa16(&Bh[0][br*264 + bwseg*8], W + (size_t)br*DMODEL + bwseg*8);
    }
    cp_commit();

    int buf = 0;
    for (int k0 = 0; k0 < K; k0 += 32) {
        bool more = (k0 + 32) < K;
        if (more) {
            int nb = buf ^ 1;
            cpa16(&Ah[nb][arow*40 + aseg*8], Abase + k0 + 32 + aseg*8);
#pragma unroll
            for (int j = 0; j < 4; j++) {
                int br = j*8 + bwrow;
                cpa16(&Bh[nb][br*264 + bwseg*8], W + (size_t)(k0 + 32 + br)*DMODEL + bwseg*8);
            }
            cp_commit();
            cp_wait1();
        } else {
            cp_wait0();
        }
        __syncthreads();

#pragma unroll
        for (int ks = 0; ks < 2; ks++) {
            unsigned af[2][4];
#pragma unroll
            for (int mt = 0; mt < 2; mt++)
                ldsm4(af[mt], &Ah[buf][(wm + mt*16 + (g8 & 1)*8 + il8)*40 + ks*16 + (g8 >> 1)*8]);
#pragma unroll
            for (int ntp = 0; ntp < 4; ntp++) {
                unsigned bbm[4];
                ldsm4t(bbm, &Bh[buf][(ks*16 + (lane & 15))*264 + wn + ntp*16 + (lane >> 4)*8]);
#pragma unroll
                for (int mt = 0; mt < 2; mt++) {
                    mma_h(acc[mt][2*ntp],   af[mt], bbm[0], bbm[1]);
                    mma_h(acc[mt][2*ntp+1], af[mt], bbm[2], bbm[3]);
                }
            }
        }
        __syncthreads();
        buf ^= 1;
    }

#pragma unroll
    for (int mt = 0; mt < 2; mt++) {
        int r0g = bm + wm + mt*16 + q;
        float s1a = 0.f, s2a = 0.f, s1b = 0.f, s2b = 0.f;
#pragma unroll
        for (int nt = 0; nt < 8; nt++) {
            int c0 = wn + nt*8 + 2*t;
            float b0 = bias[c0], b1 = bias[c0+1];
            float2 h0 = *(const float2*)&h[(size_t)r0g*DMODEL + c0];
            float2 h1 = *(const float2*)&h[(size_t)(r0g+8)*DMODEL + c0];
            acc[mt][nt][0] += b0 + h0.x; acc[mt][nt][1] += b1 + h0.y;
            acc[mt][nt][2] += b0 + h1.x; acc[mt][nt][3] += b1 + h1.y;
            s1a += acc[mt][nt][0] + acc[mt][nt][1];
            s2a += acc[mt][nt][0]*acc[mt][nt][0] + acc[mt][nt][1]*acc[mt][nt][1];
            s1b += acc[mt][nt][2] + acc[mt][nt][3];
            s2b += acc[mt][nt][2]*acc[mt][nt][2] + acc[mt][nt][3]*acc[mt][nt][3];
        }
        s1a += __shfl_xor_sync(0xffffffffu, s1a, 1); s1a += __shfl_xor_sync(0xffffffffu, s1a, 2);
        s2a += __shfl_xor_sync(0xffffffffu, s2a, 1); s2a += __shfl_xor_sync(0xffffffffu, s2a, 2);
        s1b += __shfl_xor_sync(0xffffffffu, s1b, 1); s1b += __shfl_xor_sync(0xffffffffu, s1b, 2);
        s2b += __shfl_xor_sync(0xffffffffu, s2b, 1); s2b += __shfl_xor_sync(0xffffffffu, s2b, 2);
        if (t == 0) {
            int rl = wm + mt*16 + q;
            red1[rl*4 + (warp & 3)]     = s1a;
            red2[rl*4 + (warp & 3)]     = s2a;
            red1[(rl+8)*4 + (warp & 3)] = s1b;
            red2[(rl+8)*4 + (warp & 3)] = s2b;
        }
    }
    __syncthreads();

#pragma unroll
    for (int mt = 0; mt < 2; mt++) {
        int rl = wm + mt*16 + q;
        int r0g = bm + rl;
        float t1a = red1[rl*4] + red1[rl*4+1] + red1[rl*4+2] + red1[rl*4+3];
        float t2a = red2[rl*4] + red2[rl*4+1] + red2[rl*4+2] + red2[rl*4+3];
        float t1b = red1[(rl+8)*4] + red1[(rl+8)*4+1] + red1[(rl+8)*4+2] + red1[(rl+8)*4+3];
        float t2b = red2[(rl+8)*4] + red2[(rl+8)*4+1] + red2[(rl+8)*4+2] + red2[(rl+8)*4+3];
        float ma = t1a*(1.f/DMODEL), mb = t1b*(1.f/DMODEL);
        float rsa = rsqrtf(t2a*(1.f/DMODEL) - ma*ma + 1e-5f);
        float rsb = rsqrtf(t2b*(1.f/DMODEL) - mb*mb + 1e-5f);
#pragma unroll
        for (int nt = 0; nt < 8; nt++) {
            int c0 = wn + nt*8 + 2*t;
            float2 gv = *(const float2*)&g[c0];
            float2 bv = *(const float2*)&bb[c0];
            float y0 = (acc[mt][nt][0] - ma)*rsa*gv.x + bv.x;
            float y1 = (acc[mt][nt][1] - ma)*rsa*gv.y + bv.y;
            float y2 = (acc[mt][nt][2] - mb)*rsb*gv.x + bv.x;
            float y3 = (acc[mt][nt][3] - mb)*rsb*gv.y + bv.y;
            float2 w0; w0.x = y0; w0.y = y1;
            float2 w1; w1.x = y2; w1.y = y3;
            *(float2*)&h[(size_t)r0g*DMODEL + c0]     = w0;
            *(float2*)&h[(size_t)(r0g+8)*DMODEL + c0] = w1;
            *(unsigned*)&hh[(size_t)r0g*DMODEL + c0]     = ph2(y0, y1);
            *(unsigned*)&hh[(size_t)(r0g+8)*DMODEL + c0] = ph2(y2, y3);
        }
    }
}

// ---------------- fp32-input GEMM (once, Wf = out_w @ O_w, fp16 out), batched via z ----------------
__global__ void __launch_bounds__(256) gemm_wf(const float* __restrict__ A, const float* __restrict__ W,
                                               __half* __restrict__ C, int K, int N, int sA, int sW, int sC) {
    __shared__ unsigned As2[2][64*20];
    __shared__ __half  Bsh[2][32*136];
    A += (size_t)blockIdx.z*sA; W += (size_t)blockIdx.z*sW; C += (size_t)blockIdx.z*sC;
    int bm = blockIdx.y*64, bn = blockIdx.x*128;
    int tid = threadIdx.x, lane = tid & 31, warp = tid >> 5;
    int q = lane >> 2, t = lane & 3;
    int g8 = lane >> 3, il8 = lane & 7;
    int wm = (warp >> 2)*32, wn = (warp & 3)*32;
    float acc[2][4][4] = {};
    int arow = tid >> 2, acolf = (tid & 3)*8;
    int brow = tid >> 4, bcol = (tid & 15)*8;
    const float* Ap = A + (size_t)(bm + arow)*K + acolf;
    const float* Wp = W + (size_t)brow*N + bn + bcol;

    for (int k0 = 0; k0 < K; k0 += 32) {
        float4 a0 = *(const float4*)(Ap + k0);
        float4 a1 = *(const float4*)(Ap + k0 + 4);
        float4 b0 = *(const float4*)(Wp + (size_t)k0*N);
        float4 b1 = *(const float4*)(Wp + (size_t)k0*N + 4);
        float4 b2 = *(const float4*)(Wp + (size_t)(k0+16)*N);
        float4 b3 = *(const float4*)(Wp + (size_t)(k0+16)*N + 4);
        int buf = (k0 >> 5) & 1;
        *(uint4*)&As2[buf][arow*20 + acolf/2] =
            make_uint4(ph2(a0.x,a0.y), ph2(a0.z,a0.w), ph2(a1.x,a1.y), ph2(a1.z,a1.w));
        *(uint4*)&Bsh[buf][brow*136 + bcol] =
            make_uint4(ph2(b0.x,b0.y), ph2(b0.z,b0.w), ph2(b1.x,b1.y), ph2(b1.z,b1.w));
        *(uint4*)&Bsh[buf][(brow+16)*136 + bcol] =
            make_uint4(ph2(b2.x,b2.y), ph2(b2.z,b2.w), ph2(b3.x,b3.y), ph2(b3.z,b3.w));
        __syncthreads();
#pragma unroll
        for (int ks = 0; ks < 2; ks++) {
            unsigned af[2][4];
#pragma unroll
            for (int mt = 0; mt < 2; mt++)
                ldsm4(af[mt], &As2[buf][(wm + mt*16 + (g8 & 1)*8 + il8)*20 + ks*8 + (g8 >> 1)*4]);
#pragma unroll
            for (int ntp = 0; ntp < 2; ntp++) {
                unsigned bb[4];
                ldsm4t(bb, &Bsh[buf][(ks*16 + (lane & 15))*136 + wn + ntp*16 + (lane >> 4)*8]);
#pragma unroll
                for (int mt = 0; mt < 2; mt++) {
                    mma_h(acc[mt][2*ntp],   af[mt], bb[0], bb[1]);
                    mma_h(acc[mt][2*ntp+1], af[mt], bb[2], bb[3]);
                }
            }
        }
        __syncthreads();
    }
#pragma unroll
    for (int mt = 0; mt < 2; mt++) {
        int r0 = bm + wm + mt*16 + q;
#pragma unroll
        for (int nt = 0; nt < 4; nt++) {
            int c0 = bn + wn + nt*8 + 2*t;
            *(unsigned*)&C[(size_t)r0*N + c0]     = ph2(acc[mt][nt][0], acc[mt][nt][1]);
            *(unsigned*)&C[(size_t)(r0+8)*N + c0] = ph2(acc[mt][nt][2], acc[mt][nt][3]);
        }
    }
}

// ---------------- fp16 flash attention: 64-key loaded chunks, 2x 32-key compute sub-steps ----------------
__global__ void __launch_bounds__(128, 4) attn_h(const __half* __restrict__ qkvh,
                                                 __half* __restrict__ out) {
    __shared__ __half Q2[128*40];
    __shared__ __half K2[2][64*40];
    __shared__ __half V2[2][64*40];

    int bh = blockIdx.y; int b = bh >> 3; int h = bh & 7;
    int qbase = blockIdx.x * 128;
    int tid = threadIdx.x, lane = tid & 31, w = tid >> 5;
    int q = lane >> 2, t = lane & 3;
    int g8 = lane >> 3, il8 = lane & 7;
    const __half* base = qkvh + (size_t)b*SEQ*768;
    const float M2 = 4.0f;

#pragma unroll
    for (int j = 0; j < 4; j++) {
        int task = j*128 + tid;
        int row = task >> 2, seg = task & 3;
        cpa16(&Q2[row*40 + seg*8], base + (size_t)(qbase + row)*768 + h*DHEAD + seg*8);
    }
    cp_commit();
    // chunk 0 (64 keys) -> buffer 0
#pragma unroll
    for (int j = 0; j < 2; j++) {
        int task = j*128 + tid;
        int row = task >> 2, seg = task & 3;
        cpa16(&K2[0][row*40 + seg*8], base + (size_t)row*768 + DMODEL   + h*DHEAD + seg*8);
        cpa16(&V2[0][row*40 + seg*8], base + (size_t)row*768 + 2*DMODEL + h*DHEAD + seg*8);
    }
    cp_commit();
    cp_wait1();
    __syncthreads();

    unsigned qf[2][2][4];
#pragma unroll
    for (int mt = 0; mt < 2; mt++)
#pragma unroll
        for (int ks = 0; ks < 2; ks++)
            ldsm4(qf[mt][ks], &Q2[(w*32 + mt*16 + (g8 & 1)*8 + il8)*40 + ks*16 + (g8 >> 1)*8]);

    float accO[2][4][4] = {};
    float rsum[2][2] = {};

    int buf = 0;
    const int NCH = SEQ/64;
    for (int i = 0; i < NCH; i++) {
        if (i + 1 < NCH) {
            int nb = buf ^ 1;
            const __half* src = base + (size_t)(i + 1)*64*768;
#pragma unroll
            for (int j = 0; j < 2; j++) {
                int task = j*128 + tid;
                int row = task >> 2, seg = task & 3;
                cpa16(&K2[nb][row*40 + seg*8], src + (size_t)row*768 + DMODEL   + h*DHEAD + seg*8);
                cpa16(&V2[nb][row*40 + seg*8], src + (size_t)row*768 + 2*DMODEL + h*DHEAD + seg*8);
            }
            cp_commit();
            cp_wait1();
        } else {
            cp_wait0();
        }
        __syncthreads();

#pragma unroll
        for (int sub = 0; sub < 2; sub++) {
            const __half* Kb = &K2[buf][sub*32*40];
            const __half* Vb = &V2[buf][sub*32*40];

            float s[2][4][4] = {};
#pragma unroll
            for (int ks = 0; ks < 2; ks++) {
#pragma unroll
                for (int ntp = 0; ntp < 2; ntp++) {
                    unsigned kb[4];
                    ldsm4(kb, &Kb[(ntp*16 + ((g8 >> 1) & 1)*8 + il8)*40 + ks*16 + (g8 & 1)*8]);
#pragma unroll
                    for (int mt = 0; mt < 2; mt++) {
                        mma_h(s[mt][2*ntp],   qf[mt][ks], kb[0], kb[1]);
                        mma_h(s[mt][2*ntp+1], qf[mt][ks], kb[2], kb[3]);
                    }
                }
            }

#pragma unroll
            for (int mt = 0; mt < 2; mt++)
#pragma unroll
                for (int nt = 0; nt < 4; nt++) {
                    s[mt][nt][0] = ex2(s[mt][nt][0] - M2);
                    s[mt][nt][1] = ex2(s[mt][nt][1] - M2);
                    s[mt][nt][2] = ex2(s[mt][nt][2] - M2);
                    s[mt][nt][3] = ex2(s[mt][nt][3] - M2);
                    rsum[mt][0] += s[mt][nt][0] + s[mt][nt][1];
                    rsum[mt][1] += s[mt][nt][2] + s[mt][nt][3];
                }

#pragma unroll
            for (int ks = 0; ks < 2; ks++) {
                unsigned bbv[2][4];
#pragma unroll
                for (int ntp = 0; ntp < 2; ntp++)
                    ldsm4t(bbv[ntp], &Vb[(ks*16 + (lane & 15))*40 + ntp*16 + (lane >> 4)*8]);
#pragma unroll
                for (int mt = 0; mt < 2; mt++) {
                    unsigned pa[4];
                    pa[0] = ph2(s[mt][2*ks][0],   s[mt][2*ks][1]);
                    pa[1] = ph2(s[mt][2*ks][2],   s[mt][2*ks][3]);
                    pa[2] = ph2(s[mt][2*ks+1][0], s[mt][2*ks+1][1]);
                    pa[3] = ph2(s[mt][2*ks+1][2], s[mt][2*ks+1][3]);
#pragma unroll
                    for (int ntp = 0; ntp < 2; ntp++) {
                        mma_h(accO[mt][2*ntp],   pa, bbv[ntp][0], bbv[ntp][1]);
                        mma_h(accO[mt][2*ntp+1], pa, bbv[ntp][2], bbv[ntp][3]);
                    }
                }
            }
        }
        __syncthreads();
        buf ^= 1;
    }

#pragma unroll
    for (int mt = 0; mt < 2; mt++) {
        rsum[mt][0] += __shfl_xor_sync(0xffffffffu, rsum[mt][0], 1);
        rsum[mt][0] += __shfl_xor_sync(0xffffffffu, rsum[mt][0], 2);
        rsum[mt][1] += __shfl_xor_sync(0xffffffffu, rsum[mt][1], 1);
        rsum[mt][1] += __shfl_xor_sync(0xffffffffu, rsum[mt][1], 2);
        float il0 = 1.f/rsum[mt][0], il1 = 1.f/rsum[mt][1];
        int qr = qbase + w*32 + mt*16 + q;
#pragma unroll
        for (int nt = 0; nt < 4; nt++) {
            int cc = h*DHEAD + nt*8 + 2*t;
            *(unsigned*)&out[(size_t)(b*SEQ + qr)*DMODEL + cc]     = ph2(accO[mt][nt][0]*il0, accO[mt][nt][1]*il0);
            *(unsigned*)&out[(size_t)(b*SEQ + qr + 8)*DMODEL + cc] = ph2(accO[mt][nt][2]*il1, accO[mt][nt][3]*il1);
        }
    }
}

// ---------------- host ----------------
extern "C" void kernel_launch(void* const* d_in, const int* in_sizes, int n_in,
                              void* d_out, int out_size) {
    const float* h_in    = (const float*)d_in[0];
    const float* pos     = (const float*)d_in[1];
    const float* proj_w  = (const float*)d_in[2];
    const float* proj_b  = (const float*)d_in[3];
    const float* qkv_w   = (const float*)d_in[4];
    const float* out_w   = (const float*)d_in[5];
    const float* out_b   = (const float*)d_in[6];
    const float* O_w     = (const float*)d_in[7];
    const float* O_b     = (const float*)d_in[8];
    const float* ffn1_w  = (const float*)d_in[9];
    const float* ffn1_b  = (const float*)d_in[10];
    const float* ffn2_w  = (const float*)d_in[11];
    const float* ffn2_b  = (const float*)d_in[12];
    const float* ln1_g   = (const float*)d_in[13];
    const float* ln1_b   = (const float*)d_in[14];
    const float* ln2_g   = (const float*)d_in[15];
    const float* ln2_b   = (const float*)d_in[16];
    const float* final_w = (const float*)d_in[17];
    float* out = (float*)d_out;

    float *ph, *pcs, *pbf;
    __half *phh, *pqkvh, *poh, *pffnh, *pwqkv, *pwf1, *pwf2, *pwfin, *pwWf;
    cudaGetSymbolAddress((void**)&ph,    g_h);
    cudaGetSymbolAddress((void**)&phh,   g_hh);
    cudaGetSymbolAddress((void**)&pqkvh, g_qkvh);
    cudaGetSymbolAddress((void**)&poh,   g_oh);
    cudaGetSymbolAddress((void**)&pffnh, g_ffnh);
    cudaGetSymbolAddress((void**)&pcs,   g_cs);
    cudaGetSymbolAddress((void**)&pbf,   g_bf);
    cudaGetSymbolAddress((void**)&pwqkv, g_wqkv);
    cudaGetSymbolAddress((void**)&pwf1,  g_wffn1);
    cudaGetSymbolAddress((void**)&pwf2,  g_wffn2);
    cudaGetSymbolAddress((void**)&pwfin, g_wfin);
    cudaGetSymbolAddress((void**)&pwWf,  g_wWf);

    conv_w<<<(NQ+NF1+NF2+NFW)/(256*8), 256>>>(qkv_w, ffn1_w, ffn2_w, final_w,
                                              pwqkv, pwf1, pwf2, pwfin);               // 1
    setup_kernel<<<ROWS*64/256 + ROWS*16/256, 256>>>(h_in, proj_w, proj_b, ph, phh,
                                                     pos, pcs);                        // 2
    gemm_wf<<<dim3(2,4,4), 256>>>(out_w, O_w, pwWf, DMODEL, DMODEL,
                                  DMODEL*DMODEL, DMODEL*DMODEL, DMODEL*DMODEL);        // 3

    for (int l = 0; l < NLAYER; l++) {
        gemm_hh<0,0,1,1><<<dim3(6,64), 256>>>(phh, pwqkv + (size_t)l*DMODEL*3*DMODEL,  // 4 (l=0)
                                              nullptr, pqkvh, pcs, ROWS, DMODEL, 3*DMODEL);
        attn_h<<<dim3(SEQ/128, BATCH*NHEAD), 128>>>(pqkvh, poh);                       // 5 (l=0)
        if (l == 0)
            fuse_bias_kernel<<<NLAYER, 256>>>(out_b, O_w, O_b, pbf);
        gemm_ln<<<ROWS/64, 256>>>(poh, pwWf + (size_t)l*DMODEL*DMODEL, pbf + l*DMODEL,
                                  ln1_g + l*DMODEL, ln1_b + l*DMODEL, ph, phh, DMODEL);
        gemm_hh<1,1,1,0><<<dim3(4,64), 256>>>(phh, pwf1 + (size_t)l*DMODEL*2*DMODEL,
                                              ffn1_b + l*2*DMODEL, pffnh, nullptr, ROWS, DMODEL, 2*DMODEL);
        gemm_ln<<<ROWS/64, 256>>>(pffnh, pwf2 + (size_t)l*2*DMODEL*DMODEL, ffn2_b + l*DMODEL,
                                  ln2_g + l*DMODEL, ln2_b + l*DMODEL, ph, phh, 2*DMODEL);
    }
    gemm_hh<0,0,0,0><<<dim3(2,64), 256>>>(phh, pwfin, nullptr, out, nullptr, ROWS, DMODEL, DMODEL);
}

// round 17
// speedup vs baseline: 1.0481x; 1.0481x over previous
#include <cuda_runtime.h>
#include <cuda_fp16.h>
#include <math.h>

#define BATCH 4
#define SEQ 2048
#define DMODEL 256
#define NHEAD 8
#define DHEAD 32
#define NLAYER 4
#define ROWS (BATCH*SEQ)   // 8192

// ---------------- scratch ----------------
__device__ float  g_h   [ROWS*DMODEL];
__device__ __half g_hh  [ROWS*DMODEL];
__device__ __half g_qkvh[ROWS*3*DMODEL];
__device__ __half g_oh  [ROWS*DMODEL];
__device__ __half g_ffnh[ROWS*2*DMODEL];
__device__ float  g_cs  [ROWS*32];
__device__ float  g_bf  [NLAYER*DMODEL];
__device__ __half g_wqkv [NLAYER*DMODEL*3*DMODEL];
__device__ __half g_wffn1[NLAYER*DMODEL*2*DMODEL];
__device__ __half g_wffn2[NLAYER*2*DMODEL*DMODEL];
__device__ __half g_wfin [DMODEL*DMODEL];
__device__ __half g_wWf  [NLAYER*DMODEL*DMODEL];

// ---------------- helpers ----------------
__device__ __forceinline__ unsigned ph2(float a, float b) {
    __half2 h = __floats2half2_rn(a, b);
    return *reinterpret_cast<unsigned*>(&h);
}

__device__ __forceinline__ float ex2(float x) {
    float y; asm("ex2.approx.ftz.f32 %0, %1;" : "=f"(y) : "f"(x)); return y;
}

__device__ __forceinline__ void mma_h(float* d, const unsigned* a, unsigned b0, unsigned b1) {
    asm("mma.sync.aligned.m16n8k16.row.col.f32.f16.f16.f32 "
        "{%0,%1,%2,%3},{%4,%5,%6,%7},{%8,%9},{%0,%1,%2,%3};"
        : "+f"(d[0]), "+f"(d[1]), "+f"(d[2]), "+f"(d[3])
        : "r"(a[0]), "r"(a[1]), "r"(a[2]), "r"(a[3]), "r"(b0), "r"(b1));
}

__device__ __forceinline__ void ldsm4(unsigned* r, const void* p) {
    unsigned a = (unsigned)__cvta_generic_to_shared(p);
    asm volatile("ldmatrix.sync.aligned.m8n8.x4.shared.b16 {%0,%1,%2,%3}, [%4];"
        : "=r"(r[0]), "=r"(r[1]), "=r"(r[2]), "=r"(r[3]) : "r"(a));
}

__device__ __forceinline__ void ldsm4t(unsigned* r, const void* p) {
    unsigned a = (unsigned)__cvta_generic_to_shared(p);
    asm volatile("ldmatrix.sync.aligned.m8n8.x4.trans.shared.b16 {%0,%1,%2,%3}, [%4];"
        : "=r"(r[0]), "=r"(r[1]), "=r"(r[2]), "=r"(r[3]) : "r"(a));
}

__device__ __forceinline__ void cpa16(void* smem, const void* gmem) {
    unsigned s = (unsigned)__cvta_generic_to_shared(smem);
    asm volatile("cp.async.ca.shared.global [%0], [%1], 16;" :: "r"(s), "l"(gmem));
}
__device__ __forceinline__ void cp_commit() { asm volatile("cp.async.commit_group;"); }
__device__ __forceinline__ void cp_wait0() { asm volatile("cp.async.wait_group 0;"); }
__device__ __forceinline__ void cp_wait1() { asm volatile("cp.async.wait_group 1;"); }

// ---------------- one-shot weight conversion fp32 -> fp16 ----------------
#define NQ  (NLAYER*DMODEL*3*DMODEL)
#define NF1 (NLAYER*DMODEL*2*DMODEL)
#define NF2 (NLAYER*2*DMODEL*DMODEL)
#define NFW (DMODEL*DMODEL)
__global__ void conv_w(const float* __restrict__ qw, const float* __restrict__ f1,
                       const float* __restrict__ f2, const float* __restrict__ fw,
                       __half* __restrict__ dq, __half* __restrict__ d1,
                       __half* __restrict__ d2, __half* __restrict__ df) {
    int i = (blockIdx.x*256 + threadIdx.x)*8;
    const float* s; __half* d;
    if (i < NQ)                { s = qw + i;                  d = dq + i; }
    else if (i < NQ+NF1)       { s = f1 + (i-NQ);             d = d1 + (i-NQ); }
    else if (i < NQ+NF1+NF2)   { s = f2 + (i-NQ-NF1);         d = d2 + (i-NQ-NF1); }
    else                       { s = fw + (i-NQ-NF1-NF2);     d = df + (i-NQ-NF1-NF2); }
    float4 a = *(const float4*)s;
    float4 b = *(const float4*)(s + 4);
    *(uint4*)d = make_uint4(ph2(a.x,a.y), ph2(a.z,a.w), ph2(b.x,b.y), ph2(b.z,b.w));
}

// ---------------- fused setup: proj (+fp16 mirror) + freqs ----------------
__global__ void setup_kernel(const float* __restrict__ hin, const float* __restrict__ pw,
                             const float* __restrict__ pb, float* __restrict__ hout,
                             __half* __restrict__ houth,
                             const float* __restrict__ pos, float* __restrict__ cs) {
    int bid = blockIdx.x;
    if (bid < ROWS*64/256) {
        int idx = bid*256 + threadIdx.x;
        int row = idx >> 6, c4 = idx & 63;
        float4 w = ((const float4*)pw)[c4];
        float4 b = ((const float4*)pb)[c4];
        float hv = hin[row];
        float4 r; r.x = hv*w.x + b.x; r.y = hv*w.y + b.y; r.z = hv*w.z + b.z; r.w = hv*w.w + b.w;
        ((float4*)hout)[row*64 + c4] = r;
        *(uint2*)&houth[row*DMODEL + c4*4] = make_uint2(ph2(r.x,r.y), ph2(r.z,r.w));
    } else {
        int idx = (bid - ROWS*64/256)*256 + threadIdx.x;
        int row = idx >> 4; int r = idx & 15; int axis = r >> 3; int fi = r & 7;
        float coord = pos[row*2 + axis];
        float inv = powf(10000.f, -(float)fi * 0.125f);
        float ang = coord * 64.f * inv;
        float s, c; sincosf(ang, &s, &c);
        cs[row*32 + axis*16 + fi]     = c;
        cs[row*32 + axis*16 + 8 + fi] = s;
    }
}

__global__ void fuse_bias_kernel(const float* __restrict__ out_b, const float* __restrict__ O_w,
                                 const float* __restrict__ O_b, float* __restrict__ bf) {
    int l = blockIdx.x, j = threadIdx.x;
    const float* wb = O_w + (size_t)l*DMODEL*DMODEL;
    const float* ob = out_b + l*DMODEL;
    float acc = O_b[l*DMODEL + j];
    for (int i = 0; i < DMODEL; i++) acc = fmaf(ob[i], wb[i*DMODEL + j], acc);
    bf[l*DMODEL + j] = acc;
}

// ---------------- pure-fp16 GEMM with optional fused rope epilogue ----------------
template<int HASB, int RELU, int OUTH, int ROPE>
__global__ void __launch_bounds__(256) gemm_hh(const __half* __restrict__ A, const __half* __restrict__ W,
                                               const float* __restrict__ bias, void* __restrict__ Cv,
                                               const float* __restrict__ cs,
                                               int M, int K, int N) {
    __shared__ __half Ah[2][128*40];
    __shared__ __half Bh[2][32*136];
    int bm = blockIdx.y*128, bn = blockIdx.x*128;
    int tid = threadIdx.x, lane = tid & 31, warp = tid >> 5;
    int q = lane >> 2, t = lane & 3;
    int g8 = lane >> 3, il8 = lane & 7;
    int wm = (warp >> 2)*64, wn = (warp & 3)*32;
    float acc[4][4][4] = {};

    int arow = tid >> 1, aseg = (tid & 1)*2;
    int brow = tid >> 4, bseg = tid & 15;
    const __half* Abase = A + (size_t)(bm + arow)*K;
    const __half* Wb0 = W + (size_t)brow*N + bn + bseg*8;
    const __half* Wb1 = W + (size_t)(brow + 16)*N + bn + bseg*8;

    cpa16(&Ah[0][arow*40 + aseg*8],     Abase + aseg*8);
    cpa16(&Ah[0][arow*40 + (aseg+1)*8], Abase + (aseg+1)*8);
    cpa16(&Bh[0][brow*136 + bseg*8], Wb0);
    cpa16(&Bh[0][(brow+16)*136 + bseg*8], Wb1);
    cp_commit();

    int buf = 0;
    for (int k0 = 0; k0 < K; k0 += 32) {
        bool more = (k0 + 32) < K;
        if (more) {
            int nb = buf ^ 1;
            cpa16(&Ah[nb][arow*40 + aseg*8],     Abase + k0 + 32 + aseg*8);
            cpa16(&Ah[nb][arow*40 + (aseg+1)*8], Abase + k0 + 32 + (aseg+1)*8);
            cpa16(&Bh[nb][brow*136 + bseg*8],      Wb0 + (size_t)(k0+32)*N);
            cpa16(&Bh[nb][(brow+16)*136 + bseg*8], Wb1 + (size_t)(k0+32)*N);
            cp_commit();
            cp_wait1();
        } else {
            cp_wait0();
        }
        __syncthreads();

#pragma unroll
        for (int ks = 0; ks < 2; ks++) {
            unsigned af[4][4];
#pragma unroll
            for (int mt = 0; mt < 4; mt++)
                ldsm4(af[mt], &Ah[buf][(wm + mt*16 + (g8 & 1)*8 + il8)*40 + ks*16 + (g8 >> 1)*8]);
#pragma unroll
            for (int ntp = 0; ntp < 2; ntp++) {
                unsigned bb[4];
                ldsm4t(bb, &Bh[buf][(ks*16 + (lane & 15))*136 + wn + ntp*16 + (lane >> 4)*8]);
#pragma unroll
                for (int mt = 0; mt < 4; mt++) {
                    mma_h(acc[mt][2*ntp],   af[mt], bb[0], bb[1]);
                    mma_h(acc[mt][2*ntp+1], af[mt], bb[2], bb[3]);
                }
            }
        }
        __syncthreads();
        buf ^= 1;
    }

    if (ROPE && bn < 512) {
        float scl = (bn < 256) ? 0.25503472f : 1.0f;
        __half* Ch = (__half*)Cv;
#pragma unroll
        for (int mt = 0; mt < 4; mt++) {
            int r0 = bm + wm + mt*16 + q;
            const float* cr0 = cs + (size_t)r0*32;
            const float* cr1 = cs + (size_t)(r0+8)*32;
#pragma unroll
            for (int pp = 0; pp < 2; pp++) {
                int lo = pp*2, hi = pp*2 + 1;
                int off = pp*16 + 2*t;
                float2 c0p = *(const float2*)&cr0[off];
                float2 s0p = *(const float2*)&cr0[off+8];
                float2 c1p = *(const float2*)&cr1[off];
                float2 s1p = *(const float2*)&cr1[off+8];
                float l0 = acc[mt][lo][0], l1 = acc[mt][lo][1];
                float l2 = acc[mt][lo][2], l3 = acc[mt][lo][3];
                float u0 = acc[mt][hi][0], u1 = acc[mt][hi][1];
                float u2 = acc[mt][hi][2], u3 = acc[mt][hi][3];
                float nl0 = (l0*c0p.x - u0*s0p.x)*scl, nl1 = (l1*c0p.y - u1*s0p.y)*scl;
                float nl2 = (l2*c1p.x - u2*s1p.x)*scl, nl3 = (l3*c1p.y - u3*s1p.y)*scl;
                float nu0 = (u0*c0p.x + l0*s0p.x)*scl, nu1 = (u1*c0p.y + l1*s0p.y)*scl;
                float nu2 = (u2*c1p.x + l2*s1p.x)*scl, nu3 = (u3*c1p.y + l3*s1p.y)*scl;
                int cl = bn + wn + lo*8 + 2*t;
                int ch = bn + wn + hi*8 + 2*t;
                *(unsigned*)&Ch[(size_t)r0*N + cl]     = ph2(nl0, nl1);
                *(unsigned*)&Ch[(size_t)(r0+8)*N + cl] = ph2(nl2, nl3);
                *(unsigned*)&Ch[(size_t)r0*N + ch]     = ph2(nu0, nu1);
                *(unsigned*)&Ch[(size_t)(r0+8)*N + ch] = ph2(nu2, nu3);
            }
        }
        return;
    }

#pragma unroll
    for (int mt = 0; mt < 4; mt++) {
        int r0 = bm + wm + mt*16 + q;
#pragma unroll
        for (int nt = 0; nt < 4; nt++) {
            int c0 = bn + wn + nt*8 + 2*t;
            float b0 = 0.f, b1 = 0.f;
            if (HASB) { b0 = bias[c0]; b1 = bias[c0+1]; }
            float v0 = acc[mt][nt][0] + b0, v1 = acc[mt][nt][1] + b1;
            float v2 = acc[mt][nt][2] + b0, v3 = acc[mt][nt][3] + b1;
            if (RELU) { v0=fmaxf(v0,0.f); v1=fmaxf(v1,0.f); v2=fmaxf(v2,0.f); v3=fmaxf(v3,0.f); }
            if (OUTH) {
                __half* Ch = (__half*)Cv;
                *(unsigned*)&Ch[(size_t)r0*N + c0]     = ph2(v0, v1);
                *(unsigned*)&Ch[(size_t)(r0+8)*N + c0] = ph2(v2, v3);
            } else {
                float* C = (float*)Cv;
                float2 w0; w0.x = v0; w0.y = v1;
                float2 w1; w1.x = v2; w1.y = v3;
                *(float2*)&C[(size_t)r0*N + c0]     = w0;
                *(float2*)&C[(size_t)(r0+8)*N + c0] = w1;
            }
        }
    }
}

// ---------------- fused GEMM + bias + residual + LN ----------------
__global__ void __launch_bounds__(256) gemm_ln(const __half* __restrict__ A, const __half* __restrict__ W,
                                               const float* __restrict__ bias,
                                               const float* __restrict__ g, const float* __restrict__ bb,
                                               float* __restrict__ h, __half* __restrict__ hh, int K) {
    __shared__ __half Ah[2][64*40];
    __shared__ __half Bh[2][32*264];
    __shared__ float red1[64*4], red2[64*4];
    int bm = blockIdx.x*64;
    int tid = threadIdx.x, lane = tid & 31, warp = tid >> 5;
    int q = lane >> 2, t = lane & 3;
    int g8 = lane >> 3, il8 = lane & 7;
    int wm = (warp >> 2)*32, wn = (warp & 3)*64;
    float acc[2][8][4] = {};

    int arow = tid >> 2, aseg = tid & 3;
    const __half* Abase = A + (size_t)(bm + arow)*K;
    int bwrow = warp, bwseg = lane;

    cpa16(&Ah[0][arow*40 + aseg*8], Abase + aseg*8);
#pragma unroll
    for (int j = 0; j < 4; j++) {
        int br = j*8 + bwrow;
        cpa16(&Bh[0][br*264 + bwseg*8], W + (size_t)br*DMODEL + bwseg*8);
    }
    cp_commit();

    int buf = 0;
    for (int k0 = 0; k0 < K; k0 += 32) {
        bool more = (k0 + 32) < K;
        if (more) {
            int nb = buf ^ 1;
            cpa16(&Ah[nb][arow*40 + aseg*8], Abase + k0 + 32 + aseg*8);
#pragma unroll
            for (int j = 0; j < 4; j++) {
                int br = j*8 + bwrow;
                cpa16(&Bh[nb][br*264 + bwseg*8], W + (size_t)(k0 + 32 + br)*DMODEL + bwseg*8);
            }
            cp_commit();
            cp_wait1();
        } else {
            cp_wait0();
        }
        __syncthreads();

#pragma unroll
        for (int ks = 0; ks < 2; ks++) {
            unsigned af[2][4];
#pragma unroll
            for (int mt = 0; mt < 2; mt++)
                ldsm4(af[mt], &Ah[buf][(wm + mt*16 + (g8 & 1)*8 + il8)*40 + ks*16 + (g8 >> 1)*8]);
#pragma unroll
            for (int ntp = 0; ntp < 4; ntp++) {
                unsigned bbm[4];
                ldsm4t(bbm, &Bh[buf][(ks*16 + (lane & 15))*264 + wn + ntp*16 + (lane >> 4)*8]);
#pragma unroll
                for (int mt = 0; mt < 2; mt++) {
                    mma_h(acc[mt][2*ntp],   af[mt], bbm[0], bbm[1]);
                    mma_h(acc[mt][2*ntp+1], af[mt], bbm[2], bbm[3]);
                }
            }
        }
        __syncthreads();
        buf ^= 1;
    }

#pragma unroll
    for (int mt = 0; mt < 2; mt++) {
        int r0g = bm + wm + mt*16 + q;
        float s1a = 0.f, s2a = 0.f, s1b = 0.f, s2b = 0.f;
#pragma unroll
        for (int nt = 0; nt < 8; nt++) {
            int c0 = wn + nt*8 + 2*t;
            float b0 = bias[c0], b1 = bias[c0+1];
            float2 h0 = *(const float2*)&h[(size_t)r0g*DMODEL + c0];
            float2 h1 = *(const float2*)&h[(size_t)(r0g+8)*DMODEL + c0];
            acc[mt][nt][0] += b0 + h0.x; acc[mt][nt][1] += b1 + h0.y;
            acc[mt][nt][2] += b0 + h1.x; acc[mt][nt][3] += b1 + h1.y;
            s1a += acc[mt][nt][0] + acc[mt][nt][1];
            s2a += acc[mt][nt][0]*acc[mt][nt][0] + acc[mt][nt][1]*acc[mt][nt][1];
            s1b += acc[mt][nt][2] + acc[mt][nt][3];
            s2b += acc[mt][nt][2]*acc[mt][nt][2] + acc[mt][nt][3]*acc[mt][nt][3];
        }
        s1a += __shfl_xor_sync(0xffffffffu, s1a, 1); s1a += __shfl_xor_sync(0xffffffffu, s1a, 2);
        s2a += __shfl_xor_sync(0xffffffffu, s2a, 1); s2a += __shfl_xor_sync(0xffffffffu, s2a, 2);
        s1b += __shfl_xor_sync(0xffffffffu, s1b, 1); s1b += __shfl_xor_sync(0xffffffffu, s1b, 2);
        s2b += __shfl_xor_sync(0xffffffffu, s2b, 1); s2b += __shfl_xor_sync(0xffffffffu, s2b, 2);
        if (t == 0) {
            int rl = wm + mt*16 + q;
            red1[rl*4 + (warp & 3)]     = s1a;
            red2[rl*4 + (warp & 3)]     = s2a;
            red1[(rl+8)*4 + (warp & 3)] = s1b;
            red2[(rl+8)*4 + (warp & 3)] = s2b;
        }
    }
    __syncthreads();

#pragma unroll
    for (int mt = 0; mt < 2; mt++) {
        int rl = wm + mt*16 + q;
        int r0g = bm + rl;
        float t1a = red1[rl*4] + red1[rl*4+1] + red1[rl*4+2] + red1[rl*4+3];
        float t2a = red2[rl*4] + red2[rl*4+1] + red2[rl*4+2] + red2[rl*4+3];
        float t1b = red1[(rl+8)*4] + red1[(rl+8)*4+1] + red1[(rl+8)*4+2] + red1[(rl+8)*4+3];
        float t2b = red2[(rl+8)*4] + red2[(rl+8)*4+1] + red2[(rl+8)*4+2] + red2[(rl+8)*4+3];
        float ma = t1a*(1.f/DMODEL), mb = t1b*(1.f/DMODEL);
        float rsa = rsqrtf(t2a*(1.f/DMODEL) - ma*ma + 1e-5f);
        float rsb = rsqrtf(t2b*(1.f/DMODEL) - mb*mb + 1e-5f);
#pragma unroll
        for (int nt = 0; nt < 8; nt++) {
            int c0 = wn + nt*8 + 2*t;
            float2 gv = *(const float2*)&g[c0];
            float2 bv = *(const float2*)&bb[c0];
            float y0 = (acc[mt][nt][0] - ma)*rsa*gv.x + bv.x;
            float y1 = (acc[mt][nt][1] - ma)*rsa*gv.y + bv.y;
            float y2 = (acc[mt][nt][2] - mb)*rsb*gv.x + bv.x;
            float y3 = (acc[mt][nt][3] - mb)*rsb*gv.y + bv.y;
            float2 w0; w0.x = y0; w0.y = y1;
            float2 w1; w1.x = y2; w1.y = y3;
            *(float2*)&h[(size_t)r0g*DMODEL + c0]     = w0;
            *(float2*)&h[(size_t)(r0g+8)*DMODEL + c0] = w1;
            *(unsigned*)&hh[(size_t)r0g*DMODEL + c0]     = ph2(y0, y1);
            *(unsigned*)&hh[(size_t)(r0g+8)*DMODEL + c0] = ph2(y2, y3);
        }
    }
}

// ---------------- fp32-input GEMM (once, Wf = out_w @ O_w, fp16 out), batched via z ----------------
__global__ void __launch_bounds__(256) gemm_wf(const float* __restrict__ A, const float* __restrict__ W,
                                               __half* __restrict__ C, int K, int N, int sA, int sW, int sC) {
    __shared__ unsigned As2[2][64*20];
    __shared__ __half  Bsh[2][32*136];
    A += (size_t)blockIdx.z*sA; W += (size_t)blockIdx.z*sW; C += (size_t)blockIdx.z*sC;
    int bm = blockIdx.y*64, bn = blockIdx.x*128;
    int tid = threadIdx.x, lane = tid & 31, warp = tid >> 5;
    int q = lane >> 2, t = lane & 3;
    int g8 = lane >> 3, il8 = lane & 7;
    int wm = (warp >> 2)*32, wn = (warp & 3)*32;
    float acc[2][4][4] = {};
    int arow = tid >> 2, acolf = (tid & 3)*8;
    int brow = tid >> 4, bcol = (tid & 15)*8;
    const float* Ap = A + (size_t)(bm + arow)*K + acolf;
    const float* Wp = W + (size_t)brow*N + bn + bcol;

    for (int k0 = 0; k0 < K; k0 += 32) {
        float4 a0 = *(const float4*)(Ap + k0);
        float4 a1 = *(const float4*)(Ap + k0 + 4);
        float4 b0 = *(const float4*)(Wp + (size_t)k0*N);
        float4 b1 = *(const float4*)(Wp + (size_t)k0*N + 4);
        float4 b2 = *(const float4*)(Wp + (size_t)(k0+16)*N);
        float4 b3 = *(const float4*)(Wp + (size_t)(k0+16)*N + 4);
        int buf = (k0 >> 5) & 1;
        *(uint4*)&As2[buf][arow*20 + acolf/2] =
            make_uint4(ph2(a0.x,a0.y), ph2(a0.z,a0.w), ph2(a1.x,a1.y), ph2(a1.z,a1.w));
        *(uint4*)&Bsh[buf][brow*136 + bcol] =
            make_uint4(ph2(b0.x,b0.y), ph2(b0.z,b0.w), ph2(b1.x,b1.y), ph2(b1.z,b1.w));
        *(uint4*)&Bsh[buf][(brow+16)*136 + bcol] =
            make_uint4(ph2(b2.x,b2.y), ph2(b2.z,b2.w), ph2(b3.x,b3.y), ph2(b3.z,b3.w));
        __syncthreads();
#pragma unroll
        for (int ks = 0; ks < 2; ks++) {
            unsigned af[2][4];
#pragma unroll
            for (int mt = 0; mt < 2; mt++)
                ldsm4(af[mt], &As2[buf][(wm + mt*16 + (g8 & 1)*8 + il8)*20 + ks*8 + (g8 >> 1)*4]);
#pragma unroll
            for (int ntp = 0; ntp < 2; ntp++) {
                unsigned bb[4];
                ldsm4t(bb, &Bsh[buf][(ks*16 + (lane & 15))*136 + wn + ntp*16 + (lane >> 4)*8]);
#pragma unroll
                for (int mt = 0; mt < 2; mt++) {
                    mma_h(acc[mt][2*ntp],   af[mt], bb[0], bb[1]);
                    mma_h(acc[mt][2*ntp+1], af[mt], bb[2], bb[3]);
                }
            }
        }
        __syncthreads();
    }
#pragma unroll
    for (int mt = 0; mt < 2; mt++) {
        int r0 = bm + wm + mt*16 + q;
#pragma unroll
        for (int nt = 0; nt < 4; nt++) {
            int c0 = bn + wn + nt*8 + 2*t;
            *(unsigned*)&C[(size_t)r0*N + c0]     = ph2(acc[mt][nt][0], acc[mt][nt][1]);
            *(unsigned*)&C[(size_t)(r0+8)*N + c0] = ph2(acc[mt][nt][2], acc[mt][nt][3]);
        }
    }
}

// ---------------- fp16 flash attention (round-15 winner: 32-key chunks, 4 blocks/SM) ----------------
__global__ void __launch_bounds__(128, 4) attn_h(const __half* __restrict__ qkvh,
                                                 __half* __restrict__ out) {
    __shared__ __half Q2[128*40];
    __shared__ __half K2[2][32*40];
    __shared__ __half V2[2][32*40];

    int bh = blockIdx.y; int b = bh >> 3; int h = bh & 7;
    int qbase = blockIdx.x * 128;
    int tid = threadIdx.x, lane = tid & 31, w = tid >> 5;
    int q = lane >> 2, t = lane & 3;
    int g8 = lane >> 3, il8 = lane & 7;
    const __half* base = qkvh + (size_t)b*SEQ*768;
    const float M2 = 4.0f;

#pragma unroll
    for (int j = 0; j < 4; j++) {
        int task = j*128 + tid;
        int row = task >> 2, seg = task & 3;
        cpa16(&Q2[row*40 + seg*8], base + (size_t)(qbase + row)*768 + h*DHEAD + seg*8);
    }
    cp_commit();
    {
        int row = tid >> 2, seg = tid & 3;
        cpa16(&K2[0][row*40 + seg*8], base + (size_t)row*768 + DMODEL   + h*DHEAD + seg*8);
        cpa16(&V2[0][row*40 + seg*8], base + (size_t)row*768 + 2*DMODEL + h*DHEAD + seg*8);
    }
    cp_commit();
    cp_wait1();
    __syncthreads();

    unsigned qf[2][2][4];
#pragma unroll
    for (int mt = 0; mt < 2; mt++)
#pragma unroll
        for (int ks = 0; ks < 2; ks++)
            ldsm4(qf[mt][ks], &Q2[(w*32 + mt*16 + (g8 & 1)*8 + il8)*40 + ks*16 + (g8 >> 1)*8]);

    float accO[2][4][4] = {};
    float rsum[2][2] = {};

    int krow = tid >> 2, kseg = tid & 3;
    int buf = 0;
    const int NCH = SEQ/32;
    for (int i = 0; i < NCH; i++) {
        if (i + 1 < NCH) {
            int nb = buf ^ 1;
            const __half* src = base + (size_t)(i + 1)*32*768 + (size_t)krow*768;
            cpa16(&K2[nb][krow*40 + kseg*8], src + DMODEL   + h*DHEAD + kseg*8);
            cpa16(&V2[nb][krow*40 + kseg*8], src + 2*DMODEL + h*DHEAD + kseg*8);
            cp_commit();
            cp_wait1();
        } else {
            cp_wait0();
        }
        __syncthreads();

        float s[2][4][4] = {};
#pragma unroll
        for (int ks = 0; ks < 2; ks++) {
#pragma unroll
            for (int ntp = 0; ntp < 2; ntp++) {
                unsigned kb[4];
                ldsm4(kb, &K2[buf][(ntp*16 + ((g8 >> 1) & 1)*8 + il8)*40 + ks*16 + (g8 & 1)*8]);
#pragma unroll
                for (int mt = 0; mt < 2; mt++) {
                    mma_h(s[mt][2*ntp],   qf[mt][ks], kb[0], kb[1]);
                    mma_h(s[mt][2*ntp+1], qf[mt][ks], kb[2], kb[3]);
                }
            }
        }

#pragma unroll
        for (int mt = 0; mt < 2; mt++)
#pragma unroll
            for (int nt = 0; nt < 4; nt++) {
                s[mt][nt][0] = ex2(s[mt][nt][0] - M2);
                s[mt][nt][1] = ex2(s[mt][nt][1] - M2);
                s[mt][nt][2] = ex2(s[mt][nt][2] - M2);
                s[mt][nt][3] = ex2(s[mt][nt][3] - M2);
                rsum[mt][0] += s[mt][nt][0] + s[mt][nt][1];
                rsum[mt][1] += s[mt][nt][2] + s[mt][nt][3];
            }

#pragma unroll
        for (int ks = 0; ks < 2; ks++) {
            unsigned bbv[2][4];
#pragma unroll
            for (int ntp = 0; ntp < 2; ntp++)
                ldsm4t(bbv[ntp], &V2[buf][(ks*16 + (lane & 15))*40 + ntp*16 + (lane >> 4)*8]);
#pragma unroll
            for (int mt = 0; mt < 2; mt++) {
                unsigned pa[4];
                pa[0] = ph2(s[mt][2*ks][0],   s[mt][2*ks][1]);
                pa[1] = ph2(s[mt][2*ks][2],   s[mt][2*ks][3]);
                pa[2] = ph2(s[mt][2*ks+1][0], s[mt][2*ks+1][1]);
                pa[3] = ph2(s[mt][2*ks+1][2], s[mt][2*ks+1][3]);
#pragma unroll
                for (int ntp = 0; ntp < 2; ntp++) {
                    mma_h(accO[mt][2*ntp],   pa, bbv[ntp][0], bbv[ntp][1]);
                    mma_h(accO[mt][2*ntp+1], pa, bbv[ntp][2], bbv[ntp][3]);
                }
            }
        }
        __syncthreads();
        buf ^= 1;
    }

#pragma unroll
    for (int mt = 0; mt < 2; mt++) {
        rsum[mt][0] += __shfl_xor_sync(0xffffffffu, rsum[mt][0], 1);
        rsum[mt][0] += __shfl_xor_sync(0xffffffffu, rsum[mt][0], 2);
        rsum[mt][1] += __shfl_xor_sync(0xffffffffu, rsum[mt][1], 1);
        rsum[mt][1] += __shfl_xor_sync(0xffffffffu, rsum[mt][1], 2);
        float il0 = 1.f/rsum[mt][0], il1 = 1.f/rsum[mt][1];
        int qr = qbase + w*32 + mt*16 + q;
#pragma unroll
        for (int nt = 0; nt < 4; nt++) {
            int cc = h*DHEAD + nt*8 + 2*t;
            *(unsigned*)&out[(size_t)(b*SEQ + qr)*DMODEL + cc]     = ph2(accO[mt][nt][0]*il0, accO[mt][nt][1]*il0);
            *(unsigned*)&out[(size_t)(b*SEQ + qr + 8)*DMODEL + cc] = ph2(accO[mt][nt][2]*il1, accO[mt][nt][3]*il1);
        }
    }
}

// ---------------- host ----------------
extern "C" void kernel_launch(void* const* d_in, const int* in_sizes, int n_in,
                              void* d_out, int out_size) {
    const float* h_in    = (const float*)d_in[0];
    const float* pos     = (const float*)d_in[1];
    const float* proj_w  = (const float*)d_in[2];
    const float* proj_b  = (const float*)d_in[3];
    const float* qkv_w   = (const float*)d_in[4];
    const float* out_w   = (const float*)d_in[5];
    const float* out_b   = (const float*)d_in[6];
    const float* O_w     = (const float*)d_in[7];
    const float* O_b     = (const float*)d_in[8];
    const float* ffn1_w  = (const float*)d_in[9];
    const float* ffn1_b  = (const float*)d_in[10];
    const float* ffn2_w  = (const float*)d_in[11];
    const float* ffn2_b  = (const float*)d_in[12];
    const float* ln1_g   = (const float*)d_in[13];
    const float* ln1_b   = (const float*)d_in[14];
    const float* ln2_g   = (const float*)d_in[15];
    const float* ln2_b   = (const float*)d_in[16];
    const float* final_w = (const float*)d_in[17];
    float* out = (float*)d_out;

    float *ph, *pcs, *pbf;
    __half *phh, *pqkvh, *poh, *pffnh, *pwqkv, *pwf1, *pwf2, *pwfin, *pwWf;
    cudaGetSymbolAddress((void**)&ph,    g_h);
    cudaGetSymbolAddress((void**)&phh,   g_hh);
    cudaGetSymbolAddress((void**)&pqkvh, g_qkvh);
    cudaGetSymbolAddress((void**)&poh,   g_oh);
    cudaGetSymbolAddress((void**)&pffnh, g_ffnh);
    cudaGetSymbolAddress((void**)&pcs,   g_cs);
    cudaGetSymbolAddress((void**)&pbf,   g_bf);
    cudaGetSymbolAddress((void**)&pwqkv, g_wqkv);
    cudaGetSymbolAddress((void**)&pwf1,  g_wffn1);
    cudaGetSymbolAddress((void**)&pwf2,  g_wffn2);
    cudaGetSymbolAddress((void**)&pwfin, g_wfin);
    cudaGetSymbolAddress((void**)&pwWf,  g_wWf);

    conv_w<<<(NQ+NF1+NF2+NFW)/(256*8), 256>>>(qkv_w, ffn1_w, ffn2_w, final_w,
                                              pwqkv, pwf1, pwf2, pwfin);               // 1
    setup_kernel<<<ROWS*64/256 + ROWS*16/256, 256>>>(h_in, proj_w, proj_b, ph, phh,
                                                     pos, pcs);                        // 2
    gemm_wf<<<dim3(2,4,4), 256>>>(out_w, O_w, pwWf, DMODEL, DMODEL,
                                  DMODEL*DMODEL, DMODEL*DMODEL, DMODEL*DMODEL);        // 3

    for (int l = 0; l < NLAYER; l++) {
        gemm_hh<0,0,1,1><<<dim3(6,64), 256>>>(phh, pwqkv + (size_t)l*DMODEL*3*DMODEL,  // 4 (l=0)
                                              nullptr, pqkvh, pcs, ROWS, DMODEL, 3*DMODEL);
        attn_h<<<dim3(SEQ/128, BATCH*NHEAD), 128>>>(pqkvh, poh);                       // 5 (l=0)
        if (l == 0)
            fuse_bias_kernel<<<NLAYER, 256>>>(out_b, O_w, O_b, pbf);
        gemm_ln<<<ROWS/64, 256>>>(poh, pwWf + (size_t)l*DMODEL*DMODEL, pbf + l*DMODEL,
                                  ln1_g + l*DMODEL, ln1_b + l*DMODEL, ph, phh, DMODEL);
        gemm_hh<1,1,1,0><<<dim3(4,64), 256>>>(phh, pwf1 + (size_t)l*DMODEL*2*DMODEL,
                                              ffn1_b + l*2*DMODEL, pffnh, nullptr, ROWS, DMODEL, 2*DMODEL);
        gemm_ln<<<ROWS/64, 256>>>(pffnh, pwf2 + (size_t)l*2*DMODEL*DMODEL, ffn2_b + l*DMODEL,
                                  ln2_g + l*DMODEL, ln2_b + l*DMODEL, ph, phh, 2*DMODEL);
    }
    gemm_hh<0,0,0,0><<<dim3(2,64), 256>>>(phh, pwfin, nullptr, out, nullptr, ROWS, DMODEL, DMODEL);
}